// round 4
// baseline (speedup 1.0000x reference)
#include <cuda_runtime.h>
#include <cstdint>

// MeanAggregator: out[b, :] = mean_{s<S} features[neigh_idx[b,s], :]
// B=50000, S=10, N=1e6, D=128 (fp32).
//
// One warp per output row. Each lane handles one float4 of the 128-float row:
// 32 lanes * 16B = 512B = one full feature row per LDG wave, perfectly
// coalesced. Indices preloaded into registers for MLP=10.
//
// Index dtype is detected at runtime (int32 vs int64) by a tiny kernel,
// since JAX silently downcasts int64->int32 when x64 is disabled.

#define AGG_B 50000
#define AGG_S 10
#define AGG_D 128
#define AGG_VEC (AGG_D / 4)   // 32 float4 per row == one per lane

__device__ int g_idx_is64;

__global__ void detect_idx_dtype(const unsigned int* __restrict__ idx_raw)
{
    // If the buffer is little-endian int64 with values < 2^31 (indices < 1e6),
    // every odd 32-bit word is zero. If it's int32, odd words are random
    // indices in [0, 1e6) -> essentially never all zero across 128 samples.
    int all_hi_zero = 1;
#pragma unroll 1
    for (int i = 0; i < 128; i++) {
        if (idx_raw[2 * i + 1] != 0u) { all_hi_zero = 0; break; }
    }
    g_idx_is64 = all_hi_zero;
}

__global__ __launch_bounds__(256) void mean_agg_kernel(
    const void* __restrict__ neigh_idx_raw,    // [B, S] int32 or int64
    const float4* __restrict__ features,       // [N, 32] as float4
    float4* __restrict__ out)                  // [B, 32] as float4
{
    const int gtid = blockIdx.x * blockDim.x + threadIdx.x;
    const int row  = gtid >> 5;          // warp id == output row
    const int lane = gtid & 31;          // lane == float4 column
    if (row >= AGG_B) return;

    const int is64 = g_idx_is64;

    // Preload all S indices (broadcast load: all lanes same address -> 1 txn)
    long long r[AGG_S];
    if (is64) {
        const long long* nb = (const long long*)neigh_idx_raw + (long long)row * AGG_S;
#pragma unroll
        for (int s = 0; s < AGG_S; s++) r[s] = __ldg(&nb[s]);
    } else {
        const int* nb = (const int*)neigh_idx_raw + row * AGG_S;
#pragma unroll
        for (int s = 0; s < AGG_S; s++) r[s] = (long long)__ldg(&nb[s]);
    }

    float4 acc = make_float4(0.f, 0.f, 0.f, 0.f);
#pragma unroll
    for (int s = 0; s < AGG_S; s++) {
        float4 v = __ldg(&features[r[s] * AGG_VEC + lane]);
        acc.x += v.x; acc.y += v.y; acc.z += v.z; acc.w += v.w;
    }

    const float inv = 1.0f / (float)AGG_S;
    acc.x *= inv; acc.y *= inv; acc.z *= inv; acc.w *= inv;
    out[(long long)row * AGG_VEC + lane] = acc;
}

extern "C" void kernel_launch(void* const* d_in, const int* in_sizes, int n_in,
                              void* d_out, int out_size)
{
    const void*   neigh_idx = d_in[0];                 // [B, S] int32 or int64
    const float4* features  = (const float4*)d_in[1];  // fp32 [N, D]
    float4*       out       = (float4*)d_out;          // fp32 [B, D]

    detect_idx_dtype<<<1, 1>>>((const unsigned int*)neigh_idx);

    const int threads = 256;                       // 8 warps / block
    const int total_threads = AGG_B * 32;          // one warp per row
    const int blocks = (total_threads + threads - 1) / threads;
    mean_agg_kernel<<<blocks, threads>>>(neigh_idx, features, out);
}